// round 2
// baseline (speedup 1.0000x reference)
#include <cuda_runtime.h>

#define B_SZ   2
#define S_LEN  2048
#define DM     1024
#define NH     16
#define DKH    64
#define M_ROWS (B_SZ * S_LEN)   // 4096

// Scratch: split-head Q/K/V [B*H, S, d_k] and attention output [B*S, D]
__device__ __align__(16) float g_q[(size_t)B_SZ * NH * S_LEN * DKH];
__device__ __align__(16) float g_k[(size_t)B_SZ * NH * S_LEN * DKH];
__device__ __align__(16) float g_v[(size_t)B_SZ * NH * S_LEN * DKH];
__device__ __align__(16) float g_ao[(size_t)M_ROWS * DM];

// ---------------------------------------------------------------------------
// GEMM: Y = X @ W^T + bias.  X:[4096,1024], W:[1024,1024] (row-major, K-contig)
// MODE 0/1/2: write split-head layout into g_q/g_k/g_v
// MODE 3:     X = g_ao (internal), write row-major [M, DM] into Yout
// Tile 128x128xK8, 256 threads, 8x8 per thread (as two 4x4 quadrants).
// ---------------------------------------------------------------------------
template <int MODE>
__global__ void __launch_bounds__(256)
gemm_xwt(const float* __restrict__ Xin, const float* __restrict__ W,
         const float* __restrict__ bias, float* __restrict__ Yout)
{
    __shared__ float As[8][128];   // As[k][m]
    __shared__ float Bs[8][128];   // Bs[k][n]

    const float* X = (MODE == 3) ? (const float*)g_ao : Xin;

    const int tid = threadIdx.x;
    const int tx  = tid & 15;
    const int ty  = tid >> 4;
    const int bm  = blockIdx.y << 7;
    const int bn  = blockIdx.x << 7;

    const int lr = tid >> 1;         // 0..127
    const int lc = (tid & 1) << 2;   // 0 or 4

    const float* Xp = X + (size_t)(bm + lr) * DM + lc;
    const float* Wp = W + (size_t)(bn + lr) * DM + lc;

    float acc[8][8];
#pragma unroll
    for (int i = 0; i < 8; i++)
#pragma unroll
        for (int j = 0; j < 8; j++) acc[i][j] = 0.0f;

    for (int k0 = 0; k0 < DM; k0 += 8) {
        float4 xa = *(const float4*)(Xp + k0);
        float4 wa = *(const float4*)(Wp + k0);
        if (k0) __syncthreads();   // previous tile fully consumed
        As[lc + 0][lr] = xa.x; As[lc + 1][lr] = xa.y;
        As[lc + 2][lr] = xa.z; As[lc + 3][lr] = xa.w;
        Bs[lc + 0][lr] = wa.x; Bs[lc + 1][lr] = wa.y;
        Bs[lc + 2][lr] = wa.z; Bs[lc + 3][lr] = wa.w;
        __syncthreads();
#pragma unroll
        for (int kk = 0; kk < 8; kk++) {
            float4 a0 = *(const float4*)&As[kk][(ty << 2)];
            float4 a1 = *(const float4*)&As[kk][(ty << 2) + 64];
            float4 b0 = *(const float4*)&Bs[kk][(tx << 2)];
            float4 b1 = *(const float4*)&Bs[kk][(tx << 2) + 64];
            float av[8] = {a0.x, a0.y, a0.z, a0.w, a1.x, a1.y, a1.z, a1.w};
            float bv[8] = {b0.x, b0.y, b0.z, b0.w, b1.x, b1.y, b1.z, b1.w};
#pragma unroll
            for (int i = 0; i < 8; i++)
#pragma unroll
                for (int j = 0; j < 8; j++)
                    acc[i][j] = fmaf(av[i], bv[j], acc[i][j]);
        }
    }

#pragma unroll
    for (int i = 0; i < 8; i++) {
        const int m = bm + (ty << 2) + (i & 3) + ((i >> 2) << 6);
#pragma unroll
        for (int j = 0; j < 8; j++) {
            const int n = bn + (tx << 2) + (j & 3) + ((j >> 2) << 6);
            float val = acc[i][j] + bias[n];
            if (MODE <= 2) {
                const int b = m >> 11;            // m / 2048
                const int s = m & (S_LEN - 1);
                const int h = n >> 6;
                const int d = n & 63;
                float* dst = (MODE == 0) ? g_q : (MODE == 1) ? g_k : g_v;
                dst[(((size_t)(b * NH + h) * S_LEN) + s) * DKH + d] = val;
            } else {
                Yout[(size_t)m * DM + n] = val;
            }
        }
    }
}

// ---------------------------------------------------------------------------
// Flash attention, fp32. One CTA = (bh, 64-query tile). 256 threads (16x16),
// each thread owns a 4x4 micro-tile. KV tiles of 64. Online softmax.
// Smem = exactly 48KB: Qs + KPs (K, then reused for P) + Vs, each 64x64.
// XOR swizzle sw(row) = ((row>>2)&7)<<2 keeps all float4 LDS conflict-free.
// ---------------------------------------------------------------------------
__global__ void __launch_bounds__(256)
attn_fwd()
{
    __shared__ float Qs[64 * 64];
    __shared__ float KPs[64 * 64];
    __shared__ float Vs[64 * 64];

    const int tid = threadIdx.x;
    const int tx  = tid & 15;
    const int ty  = tid >> 4;
    const int bh  = blockIdx.y;          // 0..31
    const int q0  = blockIdx.x << 6;

    const float* Qb = g_q + (size_t)bh * S_LEN * DKH;
    const float* Kb = g_k + (size_t)bh * S_LEN * DKH;
    const float* Vb = g_v + (size_t)bh * S_LEN * DKH;

    const int swr = (ty & 7) << 2;   // swizzle for rows ty*4+i (Q rows / P rows)
    const int swc = (tx & 7) << 2;   // swizzle for key rows tx*4+j

    // Load Q tile (swizzled)
#pragma unroll
    for (int p = 0; p < 4; p++) {
        int idx = tid + (p << 8);
        int r   = idx >> 4;
        int c4  = (idx & 15) << 2;
        int sw  = ((r >> 2) & 7) << 2;
        float4 qv = *(const float4*)(Qb + (size_t)(q0 + r) * DKH + c4);
        *(float4*)&Qs[(r << 6) + (c4 ^ sw)] = qv;
    }

    float m_r[4], l_r[4], o_acc[4][4];
#pragma unroll
    for (int i = 0; i < 4; i++) {
        m_r[i] = -1e30f;
        l_r[i] = 0.0f;
#pragma unroll
        for (int j = 0; j < 4; j++) o_acc[i][j] = 0.0f;
    }

    __syncthreads();

    for (int kt = 0; kt < S_LEN; kt += 64) {
        // Load K (swizzled) and V tiles
#pragma unroll
        for (int p = 0; p < 4; p++) {
            int idx = tid + (p << 8);
            int r   = idx >> 4;
            int c4  = (idx & 15) << 2;
            int sw  = ((r >> 2) & 7) << 2;
            float4 kv = *(const float4*)(Kb + (size_t)(kt + r) * DKH + c4);
            float4 vv = *(const float4*)(Vb + (size_t)(kt + r) * DKH + c4);
            *(float4*)&KPs[(r << 6) + (c4 ^ sw)] = kv;
            *(float4*)&Vs[(r << 6) + c4]         = vv;
        }
        __syncthreads();

        // S = Q K^T (4x4 per thread)
        float sacc[4][4];
#pragma unroll
        for (int i = 0; i < 4; i++)
#pragma unroll
            for (int j = 0; j < 4; j++) sacc[i][j] = 0.0f;

#pragma unroll 8
        for (int d0 = 0; d0 < 64; d0 += 4) {
            float4 aq[4], bk[4];
#pragma unroll
            for (int i = 0; i < 4; i++)
                aq[i] = *(const float4*)&Qs[(((ty << 2) + i) << 6) + (d0 ^ swr)];
#pragma unroll
            for (int j = 0; j < 4; j++)
                bk[j] = *(const float4*)&KPs[(((tx << 2) + j) << 6) + (d0 ^ swc)];
#pragma unroll
            for (int i = 0; i < 4; i++) {
                const float* ai = &aq[i].x;
#pragma unroll
                for (int j = 0; j < 4; j++) {
                    const float* bj = &bk[j].x;
                    float s = sacc[i][j];
                    s = fmaf(ai[0], bj[0], s);
                    s = fmaf(ai[1], bj[1], s);
                    s = fmaf(ai[2], bj[2], s);
                    s = fmaf(ai[3], bj[3], s);
                    sacc[i][j] = s;
                }
            }
        }

        // Online softmax update (per-row reductions across the 16 tx lanes)
        float4 pst[4];
#pragma unroll
        for (int i = 0; i < 4; i++) {
            float s0 = sacc[i][0] * 0.125f;
            float s1 = sacc[i][1] * 0.125f;
            float s2 = sacc[i][2] * 0.125f;
            float s3 = sacc[i][3] * 0.125f;
            float mx = fmaxf(fmaxf(s0, s1), fmaxf(s2, s3));
#pragma unroll
            for (int off = 8; off >= 1; off >>= 1)
                mx = fmaxf(mx, __shfl_xor_sync(0xffffffffu, mx, off));
            float newm = fmaxf(m_r[i], mx);
            float p0 = __expf(s0 - newm);
            float p1 = __expf(s1 - newm);
            float p2 = __expf(s2 - newm);
            float p3 = __expf(s3 - newm);
            float rs = (p0 + p1) + (p2 + p3);
#pragma unroll
            for (int off = 8; off >= 1; off >>= 1)
                rs += __shfl_xor_sync(0xffffffffu, rs, off);
            float corr = __expf(m_r[i] - newm);
            l_r[i] = l_r[i] * corr + rs;
            m_r[i] = newm;
#pragma unroll
            for (int j = 0; j < 4; j++) o_acc[i][j] *= corr;
            pst[i] = make_float4(p0, p1, p2, p3);
        }

        __syncthreads();   // everyone done reading K from KPs
#pragma unroll
        for (int i = 0; i < 4; i++)
            *(float4*)&KPs[(((ty << 2) + i) << 6) + ((tx << 2) ^ swr)] = pst[i];
        __syncthreads();   // P visible

        // O += P V
#pragma unroll 8
        for (int c0 = 0; c0 < 64; c0 += 4) {
            float4 ap[4], vv4[4];
#pragma unroll
            for (int i = 0; i < 4; i++)
                ap[i] = *(const float4*)&KPs[(((ty << 2) + i) << 6) + (c0 ^ swr)];
#pragma unroll
            for (int t = 0; t < 4; t++)
                vv4[t] = *(const float4*)&Vs[((c0 + t) << 6) + (tx << 2)];
#pragma unroll
            for (int i = 0; i < 4; i++) {
                const float* pi = &ap[i].x;
#pragma unroll
                for (int j = 0; j < 4; j++) {
                    float o = o_acc[i][j];
                    o = fmaf(pi[0], (&vv4[0].x)[j], o);
                    o = fmaf(pi[1], (&vv4[1].x)[j], o);
                    o = fmaf(pi[2], (&vv4[2].x)[j], o);
                    o = fmaf(pi[3], (&vv4[3].x)[j], o);
                    o_acc[i][j] = o;
                }
            }
        }
        __syncthreads();   // done with KPs(P)/Vs before next tile load
    }

    // Epilogue: normalize, write [B, S, H*d_k] layout into g_ao
    const int b = bh >> 4;
    const int h = bh & 15;
#pragma unroll
    for (int i = 0; i < 4; i++) {
        float inv  = 1.0f / l_r[i];
        int   srow = q0 + (ty << 2) + i;
        float4 ov = make_float4(o_acc[i][0] * inv, o_acc[i][1] * inv,
                                o_acc[i][2] * inv, o_acc[i][3] * inv);
        *(float4*)(g_ao + ((size_t)(b * S_LEN + srow)) * DM + (h << 6) + (tx << 2)) = ov;
    }
}

// ---------------------------------------------------------------------------
extern "C" void kernel_launch(void* const* d_in, const int* in_sizes, int n_in,
                              void* d_out, int out_size)
{
    const float* q  = (const float*)d_in[0];
    const float* k  = (const float*)d_in[1];
    const float* v  = (const float*)d_in[2];
    const float* wq = (const float*)d_in[3];
    const float* bq = (const float*)d_in[4];
    const float* wk = (const float*)d_in[5];
    const float* bk = (const float*)d_in[6];
    const float* wv = (const float*)d_in[7];
    const float* bv = (const float*)d_in[8];
    const float* wo = (const float*)d_in[9];
    const float* bo = (const float*)d_in[10];
    float* out = (float*)d_out;

    dim3 gg(DM / 128, M_ROWS / 128);   // (8, 32)
    gemm_xwt<0><<<gg, 256>>>(q, wq, bq, nullptr);
    gemm_xwt<1><<<gg, 256>>>(k, wk, bk, nullptr);
    gemm_xwt<2><<<gg, 256>>>(v, wv, bv, nullptr);
    attn_fwd<<<dim3(S_LEN / 64, B_SZ * NH), 256>>>();
    gemm_xwt<3><<<gg, 256>>>(nullptr, wo, bo, out);
}